// round 6
// baseline (speedup 1.0000x reference)
#include <cuda_runtime.h>

// Shapes (fixed): O=256, I=512, K=3, C=128, B=128
// Inputs (metadata order):
//   d_in[0] x                (B=128, I=512)  f32
//   d_in[1] control_points   (O=256, 4)      f32 (unused; only k=3 matters)
//   d_in[2] control_values   (O=256, 4, C=128) f32
//   d_in[3] expansion_matrix (C=128, I=512)  f32
// Output: (O=256, B=128, T=512) f32, out[o*65536 + b*512 + t]
//
// Factorization:
//   Y[c,b]   = sum_f E[c,f] x[b,f]              (128x128x512 GEMM)
//   Z[o,k,b] = sum_c cv[o,k,c] Y[c,b]           (fused into output kernel)
//   out[o,b,t] = lerp(Z[o,j(t),b], Z[o,j(t)+1,b], tl(t))

static constexpr int C_ = 128;
static constexpr int B_ = 128;
static constexpr int I_ = 512;
static constexpr int O_ = 256;
static constexpr int T_ = 512;

// Scratch: Yt[b][c]  (b-major so output kernel reads coalesced)
__device__ float g_Yt[B_ * C_];

// ---------------------------------------------------------------------------
// Kernel 1: Yt[b][c] = sum_f x[b,f] * E[c,f]   (NT GEMM, 16x16 tiles)
// grid (8,8) = (c-tiles, b-tiles), block (16,16)
// ---------------------------------------------------------------------------
__global__ void yt_gemm_kernel(const float* __restrict__ x,
                               const float* __restrict__ E) {
    __shared__ float sX[16][17];
    __shared__ float sE[16][17];
    const int tx = threadIdx.x, ty = threadIdx.y;
    const int b = blockIdx.y * 16 + ty;          // output row (b)
    const int c_load = blockIdx.x * 16 + ty;     // row of E this thread-row loads
    float acc = 0.0f;
    for (int f0 = 0; f0 < I_; f0 += 16) {
        sX[ty][tx] = x[b * I_ + f0 + tx];
        sE[ty][tx] = E[c_load * I_ + f0 + tx];
        __syncthreads();
#pragma unroll
        for (int kk = 0; kk < 16; ++kk)
            acc = fmaf(sX[ty][kk], sE[tx][kk], acc);
        __syncthreads();
    }
    g_Yt[b * C_ + blockIdx.x * 16 + tx] = acc;
}

// ---------------------------------------------------------------------------
// Kernel 2: one block per (o,b). Compute z[k]=sum_c cv[o,k,c]*Yt[b,c] (k=0..3),
// then write out[o,b,0..511] = lerp(z[j], z[j+1], tl) as float4 per thread.
// grid 32768 blocks x 128 threads.
// ---------------------------------------------------------------------------
__global__ void __launch_bounds__(128)
spline_out_kernel(const float* __restrict__ cv, float* __restrict__ out) {
    const int bid = blockIdx.x;
    const int o = bid >> 7;        // bid / 128
    const int b = bid & 127;       // bid % 128
    const int tid = threadIdx.x;

    // Per-thread partials for the 4 control slots
    const float y = g_Yt[b * C_ + tid];
    const float* __restrict__ cvo = cv + (size_t)o * 512;  // (4,128) row-major
    float p0 = cvo[tid]         * y;
    float p1 = cvo[128 + tid]   * y;
    float p2 = cvo[256 + tid]   * y;
    float p3 = cvo[384 + tid]   * y;

    // Warp reduce
#pragma unroll
    for (int off = 16; off > 0; off >>= 1) {
        p0 += __shfl_down_sync(0xFFFFFFFFu, p0, off);
        p1 += __shfl_down_sync(0xFFFFFFFFu, p1, off);
        p2 += __shfl_down_sync(0xFFFFFFFFu, p2, off);
        p3 += __shfl_down_sync(0xFFFFFFFFu, p3, off);
    }

    __shared__ float s[4][4];
    __shared__ float z[4];
    const int lane = tid & 31;
    const int w = tid >> 5;
    if (lane == 0) { s[0][w] = p0; s[1][w] = p1; s[2][w] = p2; s[3][w] = p3; }
    __syncthreads();
    if (tid < 4) z[tid] = s[tid][0] + s[tid][1] + s[tid][2] + s[tid][3];
    __syncthreads();

    const float z0 = z[0], z1 = z[1], z2 = z[2], z3 = z[3];

    const int t0 = tid * 4;
    float v[4];
#pragma unroll
    for (int u = 0; u < 4; ++u) {
        const float ts = (float)(t0 + u) * (3.0f / 511.0f);
        int j = (int)ts;               // ts >= 0, so trunc == floor
        if (j > 2) j = 2;
        const float tl = ts - (float)j;
        const float za = (j == 0) ? z0 : ((j == 1) ? z1 : z2);
        const float zb = (j == 0) ? z1 : ((j == 1) ? z2 : z3);
        v[u] = za + tl * (zb - za);
    }
    float4 r = make_float4(v[0], v[1], v[2], v[3]);
    *reinterpret_cast<float4*>(out + (size_t)bid * T_ + t0) = r;
}

// ---------------------------------------------------------------------------
extern "C" void kernel_launch(void* const* d_in, const int* in_sizes, int n_in,
                              void* d_out, int out_size) {
    const float* x  = (const float*)d_in[0];
    const float* cv = (const float*)d_in[2];
    const float* E  = (const float*)d_in[3];
    float* out = (float*)d_out;

    dim3 g1(C_ / 16, B_ / 16);   // (8, 8)
    dim3 b1(16, 16);
    yt_gemm_kernel<<<g1, b1>>>(x, E);

    spline_out_kernel<<<O_ * B_, 128>>>(cv, out);
}